// round 7
// baseline (speedup 1.0000x reference)
#include <cuda_runtime.h>

#define NN 100000
#define NE 600000
#define DD 128
#define LL 4
#define BM 128
#define MB ((NN + BM - 1) / BM)
#define NBLK ((NN + 255) / 256)   // 391 scan blocks

#define W_PAD 136
#define A_PAD 36
// W[128][136] + A[128][36] + scale/shift[256]
#define GSMEM ((128 * W_PAD + 128 * A_PAD + 256) * 4)

// Scratch (allocation-free rule: __device__ globals)
__device__ __align__(16) float g_agg[NN * DD];
__device__ __align__(16) float g_z[NN * DD];
__device__ __align__(16) float g_h[NN * DD];
__device__ __align__(16) float g_sum[DD];
__device__ __align__(16) float g_sumsq[DD];
__device__ int g_src[NE];
__device__ int g_dst[NE];
__device__ int g_is64;
// CSR
__device__ int g_cnt[NN];
__device__ int g_roff[NN + 1];
__device__ int g_part[NBLK];
__device__ int g_poff[NBLK];
__device__ int g_cursor[NN];
__device__ int g_csr_src[NE];
__device__ __align__(16) float g_csr_a[NE];

// ---------------------------------------------------------------------------
__device__ __forceinline__ unsigned f2tf(float f) {
    unsigned u;
    asm("cvt.rna.tf32.f32 %0, %1;" : "=r"(u) : "f"(f));
    return u;
}

__device__ __forceinline__ void mma8(float* d, unsigned a0, unsigned a1,
                                     unsigned a2, unsigned a3,
                                     unsigned b0, unsigned b1) {
    asm volatile(
        "mma.sync.aligned.m16n8k8.row.col.f32.tf32.tf32.f32 "
        "{%0,%1,%2,%3},{%4,%5,%6,%7},{%8,%9},{%0,%1,%2,%3};"
        : "+f"(d[0]), "+f"(d[1]), "+f"(d[2]), "+f"(d[3])
        : "r"(a0), "r"(a1), "r"(a2), "r"(a3), "r"(b0), "r"(b1));
}

// ---------------------------------------------------------------------------
// Edge-index dtype detection (indices < 2^17: int64 layout has all-odd-words
// zero; int32 false-positive prob ~ (1e-5)^32 ~ 0).
// ---------------------------------------------------------------------------
__global__ void detect_kernel(const int* __restrict__ ei32) {
    int all0 = 1;
#pragma unroll
    for (int i = 1; i < 64; i += 2) all0 &= (ei32[i] == 0);
    g_is64 = all0;
}

// convert edge index + zero histogram counters
__global__ void convert_kernel(const void* __restrict__ ei) {
    int e = blockIdx.x * blockDim.x + threadIdx.x;
    if (e < NN) g_cnt[e] = 0;
    if (e == 0) g_roff[NN] = NE;
    if (e >= NE) return;
    if (g_is64) {
        const long long* p = (const long long*)ei;
        g_src[e] = (int)p[e];
        g_dst[e] = (int)p[NE + e];
    } else {
        const int* p = (const int*)ei;
        g_src[e] = p[e];
        g_dst[e] = p[NE + e];
    }
}

__global__ void hist_kernel() {
    int e = blockIdx.x * blockDim.x + threadIdx.x;
    if (e < NE) atomicAdd(&g_cnt[g_dst[e]], 1);
}

__global__ void scan_block_kernel() {
    __shared__ int sd[256];
    int tid = threadIdx.x;
    int i = blockIdx.x * 256 + tid;
    int v = (i < NN) ? g_cnt[i] : 0;
    sd[tid] = v;
    __syncthreads();
#pragma unroll
    for (int o = 1; o < 256; o <<= 1) {
        int t = (tid >= o) ? sd[tid - o] : 0;
        __syncthreads();
        sd[tid] += t;
        __syncthreads();
    }
    if (i < NN) g_roff[i] = sd[tid] - v;
    if (tid == 255) g_part[blockIdx.x] = sd[255];
}

__global__ void scan_part_kernel() {
    __shared__ int sd[512];
    int tid = threadIdx.x;
    int v = (tid < NBLK) ? g_part[tid] : 0;
    sd[tid] = v;
    __syncthreads();
#pragma unroll
    for (int o = 1; o < 512; o <<= 1) {
        int t = (tid >= o) ? sd[tid - o] : 0;
        __syncthreads();
        sd[tid] += t;
        __syncthreads();
    }
    if (tid < NBLK) g_poff[tid] = sd[tid] - v;
}

__global__ void scan_add_kernel() {
    int i = blockIdx.x * blockDim.x + threadIdx.x;
    if (i < NN) {
        int r = g_roff[i] + g_poff[i >> 8];
        g_roff[i] = r;
        g_cursor[i] = r;
    }
}

__global__ void fill_kernel(const float* __restrict__ ea) {
    int e = blockIdx.x * blockDim.x + threadIdx.x;
    if (e >= NE) return;
    int d = g_dst[e];
    int p = atomicAdd(&g_cursor[d], 1);
    g_csr_src[p] = g_src[e];
    g_csr_a[p] = ea[e];
}

// ---------------------------------------------------------------------------
// Gather-reduce edge phase: one warp per destination node, 4-edge unrolled
// main loop for MLP. agg[n] = (1+eps)*h[n] + sum relu(h[src]+a*We+be).
// Also zeroes the BN stat accumulators (block 0).
// ---------------------------------------------------------------------------
__global__ void __launch_bounds__(256) gather_kernel(
    const float* __restrict__ h,
    const float* __restrict__ We_l,
    const float* __restrict__ be_l,
    const float* __restrict__ eps_l) {
    if (blockIdx.x == 0 && threadIdx.x < DD) {
        g_sum[threadIdx.x] = 0.f;
        g_sumsq[threadIdx.x] = 0.f;
    }
    int node = (blockIdx.x * 256 + threadIdx.x) >> 5;
    if (node >= NN) return;
    int lane = threadIdx.x & 31;
    float4 w  = ((const float4*)We_l)[lane];
    float4 bb = ((const float4*)be_l)[lane];
    float s = 1.0f + __ldg(eps_l);
    float4 hv = ((const float4*)h)[node * 32 + lane];
    float4 acc = make_float4(s * hv.x, s * hv.y, s * hv.z, s * hv.w);

    int i = g_roff[node];
    int end = g_roff[node + 1];
    // 4-edge unrolled main loop: 4 independent L2 loads in flight
    for (; i + 4 <= end; i += 4) {
        int s0 = g_csr_src[i],     s1 = g_csr_src[i + 1];
        int s2 = g_csr_src[i + 2], s3 = g_csr_src[i + 3];
        float a0 = g_csr_a[i],     a1 = g_csr_a[i + 1];
        float a2 = g_csr_a[i + 2], a3 = g_csr_a[i + 3];
        float4 x0 = ((const float4*)h)[s0 * 32 + lane];
        float4 x1 = ((const float4*)h)[s1 * 32 + lane];
        float4 x2 = ((const float4*)h)[s2 * 32 + lane];
        float4 x3 = ((const float4*)h)[s3 * 32 + lane];
        acc.x += fmaxf(x0.x + fmaf(a0, w.x, bb.x), 0.f)
               + fmaxf(x1.x + fmaf(a1, w.x, bb.x), 0.f)
               + fmaxf(x2.x + fmaf(a2, w.x, bb.x), 0.f)
               + fmaxf(x3.x + fmaf(a3, w.x, bb.x), 0.f);
        acc.y += fmaxf(x0.y + fmaf(a0, w.y, bb.y), 0.f)
               + fmaxf(x1.y + fmaf(a1, w.y, bb.y), 0.f)
               + fmaxf(x2.y + fmaf(a2, w.y, bb.y), 0.f)
               + fmaxf(x3.y + fmaf(a3, w.y, bb.y), 0.f);
        acc.z += fmaxf(x0.z + fmaf(a0, w.z, bb.z), 0.f)
               + fmaxf(x1.z + fmaf(a1, w.z, bb.z), 0.f)
               + fmaxf(x2.z + fmaf(a2, w.z, bb.z), 0.f)
               + fmaxf(x3.z + fmaf(a3, w.z, bb.z), 0.f);
        acc.w += fmaxf(x0.w + fmaf(a0, w.w, bb.w), 0.f)
               + fmaxf(x1.w + fmaf(a1, w.w, bb.w), 0.f)
               + fmaxf(x2.w + fmaf(a2, w.w, bb.w), 0.f)
               + fmaxf(x3.w + fmaf(a3, w.w, bb.w), 0.f);
    }
    if (i + 2 <= end) {
        int s0 = g_csr_src[i], s1 = g_csr_src[i + 1];
        float a0 = g_csr_a[i], a1 = g_csr_a[i + 1];
        float4 x0 = ((const float4*)h)[s0 * 32 + lane];
        float4 x1 = ((const float4*)h)[s1 * 32 + lane];
        acc.x += fmaxf(x0.x + fmaf(a0, w.x, bb.x), 0.f)
               + fmaxf(x1.x + fmaf(a1, w.x, bb.x), 0.f);
        acc.y += fmaxf(x0.y + fmaf(a0, w.y, bb.y), 0.f)
               + fmaxf(x1.y + fmaf(a1, w.y, bb.y), 0.f);
        acc.z += fmaxf(x0.z + fmaf(a0, w.z, bb.z), 0.f)
               + fmaxf(x1.z + fmaf(a1, w.z, bb.z), 0.f);
        acc.w += fmaxf(x0.w + fmaf(a0, w.w, bb.w), 0.f)
               + fmaxf(x1.w + fmaf(a1, w.w, bb.w), 0.f);
        i += 2;
    }
    if (i < end) {
        int s0 = g_csr_src[i];
        float a0 = g_csr_a[i];
        float4 x0 = ((const float4*)h)[s0 * 32 + lane];
        acc.x += fmaxf(x0.x + fmaf(a0, w.x, bb.x), 0.f);
        acc.y += fmaxf(x0.y + fmaf(a0, w.y, bb.y), 0.f);
        acc.z += fmaxf(x0.z + fmaf(a0, w.z, bb.z), 0.f);
        acc.w += fmaxf(x0.w + fmaf(a0, w.w, bb.w), 0.f);
    }
    ((float4*)g_agg)[node * 32 + lane] = acc;
}

// ---------------------------------------------------------------------------
// tf32 tensor-core GEMM (R5-proven mainloop: single A buffer, 2 syncs/strip).
// 128x128 CTA tile, 8 warps (4M x 2N), warp 32x64.
// MODE 1: z = agg @ W + b, fused BN sum/sumsq  -> g_z
// MODE 2: BN scale/shift folded per-block from g_sum/g_sumsq, then
//         out = [res +] relu( relu(BN(z)) @ W + b ) -> outp
// ---------------------------------------------------------------------------
template <int MODE>
__global__ void __launch_bounds__(256, 2) gemm_tc(
    const float* __restrict__ W,
    const float* __restrict__ bias,
    const float* __restrict__ aux,     // MODE2: residual
    const float* __restrict__ gamma,   // MODE2 only
    const float* __restrict__ beta,    // MODE2 only
    float* __restrict__ outp,          // MODE2 only
    int add_res) {
    extern __shared__ float sm[];
    float* Ws = sm;                              // [128][W_PAD]
    float* As = sm + 128 * W_PAD;                // [128][A_PAD]
    float* s_scale = As + 128 * A_PAD;           // [128]
    float* s_shift = s_scale + 128;              // [128]
    unsigned* Wu = (unsigned*)Ws;
    unsigned* Au = (unsigned*)As;

    int tid = threadIdx.x;
    int lane = tid & 31, wid = tid >> 5;
    int wm = wid & 3, wn = wid >> 2;
    int g = lane >> 2, t = lane & 3;
    int row0 = blockIdx.x * BM;

    // ---- W -> smem (tf32) ----
    {
        int r = tid >> 5, c = lane * 4;
#pragma unroll
        for (int p = 0; p < 16; p++) {
            int row = r + p * 8;
            float4 v = *(const float4*)&W[row * DD + c];
            uint4 u = make_uint4(f2tf(v.x), f2tf(v.y), f2tf(v.z), f2tf(v.w));
            *(uint4*)&Wu[row * W_PAD + c] = u;
        }
    }
    // ---- MODE2: fold BN stats into scale/shift ----
    if (MODE == 2 && tid < DD) {
        float mu = g_sum[tid] * (1.0f / NN);
        float var = g_sumsq[tid] * (1.0f / NN) - mu * mu;
        float rs = rsqrtf(var + 1e-5f);
        float sc = rs * __ldg(&gamma[tid]);
        s_scale[tid] = sc;
        s_shift[tid] = __ldg(&beta[tid]) - mu * sc;
    }
    if (MODE == 2) __syncthreads();

    float acc[2][8][4];
#pragma unroll
    for (int mi = 0; mi < 2; mi++)
#pragma unroll
        for (int ni = 0; ni < 8; ni++)
#pragma unroll
            for (int q = 0; q < 4; q++) acc[mi][ni][q] = 0.f;

    for (int ko = 0; ko < 4; ko++) {
        __syncthreads();
        {
            int r = tid >> 3, c = (tid & 7) * 4;
#pragma unroll
            for (int p = 0; p < 4; p++) {
                int rr = r + p * 32;
                int row = row0 + rr;
                float4 v = make_float4(0.f, 0.f, 0.f, 0.f);
                if (row < NN) {
                    int off = row * DD + ko * 32 + c;
                    if (MODE == 1) {
                        v = *(const float4*)&g_agg[off];
                    } else {
                        float4 z = *(const float4*)&g_z[off];
                        float4 sc = *(const float4*)&s_scale[ko * 32 + c];
                        float4 sh = *(const float4*)&s_shift[ko * 32 + c];
                        v.x = fmaxf(fmaf(z.x, sc.x, sh.x), 0.f);
                        v.y = fmaxf(fmaf(z.y, sc.y, sh.y), 0.f);
                        v.z = fmaxf(fmaf(z.z, sc.z, sh.z), 0.f);
                        v.w = fmaxf(fmaf(z.w, sc.w, sh.w), 0.f);
                    }
                }
                uint4 u = make_uint4(f2tf(v.x), f2tf(v.y), f2tf(v.z), f2tf(v.w));
                *(uint4*)&Au[rr * A_PAD + c] = u;
            }
        }
        __syncthreads();
#pragma unroll
        for (int kk = 0; kk < 4; kk++) {
            int kb = kk * 8;
            int kw = ko * 32 + kb;
            unsigned b0[8], b1[8];
#pragma unroll
            for (int ni = 0; ni < 8; ni++) {
                int col = wn * 64 + ni * 8 + g;
                b0[ni] = Wu[(kw + t) * W_PAD + col];
                b1[ni] = Wu[(kw + t + 4) * W_PAD + col];
            }
#pragma unroll
            for (int mi = 0; mi < 2; mi++) {
                int rb = wm * 32 + mi * 16;
                unsigned a0 = Au[(rb + g) * A_PAD + kb + t];
                unsigned a1 = Au[(rb + g + 8) * A_PAD + kb + t];
                unsigned a2 = Au[(rb + g) * A_PAD + kb + t + 4];
                unsigned a3 = Au[(rb + g + 8) * A_PAD + kb + t + 4];
#pragma unroll
                for (int ni = 0; ni < 8; ni++)
                    mma8(acc[mi][ni], a0, a1, a2, a3, b0[ni], b1[ni]);
            }
        }
    }

    float bcol[16];
#pragma unroll
    for (int ni = 0; ni < 8; ni++) {
        int col = wn * 64 + ni * 8 + 2 * t;
        bcol[ni * 2]     = __ldg(&bias[col]);
        bcol[ni * 2 + 1] = __ldg(&bias[col + 1]);
    }

    if (MODE == 1) {
        float psum[16], psq[16];
#pragma unroll
        for (int i = 0; i < 16; i++) { psum[i] = 0.f; psq[i] = 0.f; }
#pragma unroll
        for (int mi = 0; mi < 2; mi++) {
            int r1 = row0 + wm * 32 + mi * 16 + g;
            int r2 = r1 + 8;
#pragma unroll
            for (int ni = 0; ni < 8; ni++) {
                int col = wn * 64 + ni * 8 + 2 * t;
                float x0 = acc[mi][ni][0] + bcol[ni * 2];
                float x1 = acc[mi][ni][1] + bcol[ni * 2 + 1];
                float x2 = acc[mi][ni][2] + bcol[ni * 2];
                float x3 = acc[mi][ni][3] + bcol[ni * 2 + 1];
                if (r1 < NN) {
                    *(float2*)&g_z[r1 * DD + col] = make_float2(x0, x1);
                    psum[ni * 2] += x0;     psq[ni * 2] += x0 * x0;
                    psum[ni * 2 + 1] += x1; psq[ni * 2 + 1] += x1 * x1;
                }
                if (r2 < NN) {
                    *(float2*)&g_z[r2 * DD + col] = make_float2(x2, x3);
                    psum[ni * 2] += x2;     psq[ni * 2] += x2 * x2;
                    psum[ni * 2 + 1] += x3; psq[ni * 2 + 1] += x3 * x3;
                }
            }
        }
#pragma unroll
        for (int d = 4; d < 32; d <<= 1) {
#pragma unroll
            for (int i = 0; i < 16; i++) {
                psum[i] += __shfl_down_sync(0xFFFFFFFFu, psum[i], d);
                psq[i]  += __shfl_down_sync(0xFFFFFFFFu, psq[i], d);
            }
        }
        __syncthreads();
        float* ssum = As;
        float* ssq  = As + DD;
        if (tid < DD) { ssum[tid] = 0.f; ssq[tid] = 0.f; }
        __syncthreads();
        if (lane < 4) {
#pragma unroll
            for (int i = 0; i < 16; i++) {
                int col = wn * 64 + (i >> 1) * 8 + 2 * t + (i & 1);
                atomicAdd(&ssum[col], psum[i]);
                atomicAdd(&ssq[col],  psq[i]);
            }
        }
        __syncthreads();
        if (tid < DD) {
            atomicAdd(&g_sum[tid],   ssum[tid]);
            atomicAdd(&g_sumsq[tid], ssq[tid]);
        }
    } else {
#pragma unroll
        for (int mi = 0; mi < 2; mi++) {
            int r1 = row0 + wm * 32 + mi * 16 + g;
            int r2 = r1 + 8;
#pragma unroll
            for (int ni = 0; ni < 8; ni++) {
                int col = wn * 64 + ni * 8 + 2 * t;
                float x0 = fmaxf(acc[mi][ni][0] + bcol[ni * 2], 0.f);
                float x1 = fmaxf(acc[mi][ni][1] + bcol[ni * 2 + 1], 0.f);
                float x2 = fmaxf(acc[mi][ni][2] + bcol[ni * 2], 0.f);
                float x3 = fmaxf(acc[mi][ni][3] + bcol[ni * 2 + 1], 0.f);
                if (r1 < NN) {
                    if (add_res) {
                        float2 rv = *(const float2*)&aux[r1 * DD + col];
                        x0 += rv.x; x1 += rv.y;
                    }
                    *(float2*)&outp[r1 * DD + col] = make_float2(x0, x1);
                }
                if (r2 < NN) {
                    if (add_res) {
                        float2 rv = *(const float2*)&aux[r2 * DD + col];
                        x2 += rv.x; x3 += rv.y;
                    }
                    *(float2*)&outp[r2 * DD + col] = make_float2(x2, x3);
                }
            }
        }
    }
}

// ---------------------------------------------------------------------------
extern "C" void kernel_launch(void* const* d_in, const int* in_sizes, int n_in,
                              void* d_out, int out_size) {
    const float* x     = (const float*)d_in[0];
    const void*  ei    = d_in[1];
    const float* ea    = (const float*)d_in[2];
    const float* We    = (const float*)d_in[3];
    const float* be    = (const float*)d_in[4];
    const float* eps   = (const float*)d_in[5];
    const float* W1    = (const float*)d_in[6];
    const float* b1    = (const float*)d_in[7];
    const float* gamma = (const float*)d_in[8];
    const float* beta  = (const float*)d_in[9];
    const float* W2    = (const float*)d_in[10];
    const float* b2    = (const float*)d_in[11];

    void* hp;
    cudaGetSymbolAddress(&hp, g_h);
    float* gh = (float*)hp;

    cudaFuncSetAttribute(gemm_tc<1>, cudaFuncAttributeMaxDynamicSharedMemorySize, GSMEM);
    cudaFuncSetAttribute(gemm_tc<2>, cudaFuncAttributeMaxDynamicSharedMemorySize, GSMEM);

    // edge-index conversion + CSR build (per launch; graph is static input)
    detect_kernel<<<1, 1>>>((const int*)ei);
    convert_kernel<<<(NE + 255) / 256, 256>>>(ei);
    hist_kernel<<<(NE + 255) / 256, 256>>>();
    scan_block_kernel<<<NBLK, 256>>>();
    scan_part_kernel<<<1, 512>>>();
    scan_add_kernel<<<NBLK, 256>>>();
    fill_kernel<<<(NE + 255) / 256, 256>>>(ea);

    for (int l = 0; l < LL; l++) {
        const float* h_in = (l == 0) ? x : gh;
        float* h_out = (l == LL - 1) ? (float*)d_out : gh;
        gather_kernel<<<(NN * 32) / 256, 256>>>(h_in, We + l * DD, be + l * DD,
                                                eps + l);
        gemm_tc<1><<<MB, 256, GSMEM>>>(W1 + l * DD * DD, b1 + l * DD,
                                       nullptr, nullptr, nullptr, nullptr, 0);
        gemm_tc<2><<<MB, 256, GSMEM>>>(W2 + l * DD * DD, b2 + l * DD,
                                       h_in, gamma + l * DD, beta + l * DD,
                                       h_out, l > 0 ? 1 : 0);
    }
}

// round 8
// speedup vs baseline: 1.4013x; 1.4013x over previous
#include <cuda_runtime.h>

#define NN 100000
#define NE 600000
#define DD 128
#define LL 4
#define BM 128
#define MB ((NN + BM - 1) / BM)
#define NBLK ((NN + 255) / 256)   // 391 scan blocks

#define W_PAD 136
#define A_PAD 36
#define GSMEM ((128 * W_PAD + 128 * A_PAD) * 4)

// Scratch (allocation-free rule: __device__ globals)
__device__ __align__(16) float g_agg[NN * DD];
__device__ __align__(16) float g_z[NN * DD];
__device__ __align__(16) float g_h[NN * DD];
__device__ __align__(16) float g_sum[DD];
__device__ __align__(16) float g_sumsq[DD];
__device__ __align__(16) float g_scale[DD];
__device__ __align__(16) float g_shift[DD];
__device__ int g_src[NE];
__device__ int g_dst[NE];
// CSR
__device__ int g_cnt[NN];
__device__ int g_roff[NN + 1];
__device__ int g_part[NBLK];
__device__ int g_poff[NBLK];
__device__ int g_cursor[NN];
__device__ int g_csr_src[NE];
__device__ __align__(16) float g_csr_a[NE];

// ---------------------------------------------------------------------------
__device__ __forceinline__ unsigned f2tf(float f) {
    unsigned u;
    asm("cvt.rna.tf32.f32 %0, %1;" : "=r"(u) : "f"(f));
    return u;
}

__device__ __forceinline__ void mma8(float* d, unsigned a0, unsigned a1,
                                     unsigned a2, unsigned a3,
                                     unsigned b0, unsigned b1) {
    asm volatile(
        "mma.sync.aligned.m16n8k8.row.col.f32.tf32.tf32.f32 "
        "{%0,%1,%2,%3},{%4,%5,%6,%7},{%8,%9},{%0,%1,%2,%3};"
        : "+f"(d[0]), "+f"(d[1]), "+f"(d[2]), "+f"(d[3])
        : "r"(a0), "r"(a1), "r"(a2), "r"(a3), "r"(b0), "r"(b1));
}

// ---------------------------------------------------------------------------
// Edge-index conversion with inline dtype detection (indices < 2^17: int64
// layout has all-odd-words zero over the first 64 words; int32 false-positive
// prob ~ (1e-5)^32 ~ 0). Each block detects independently (same answer).
// ---------------------------------------------------------------------------
__global__ void convert_kernel(const void* __restrict__ ei) {
    __shared__ int s64;
    if (threadIdx.x == 0) {
        const int* p = (const int*)ei;
        int all0 = 1;
#pragma unroll
        for (int i = 1; i < 64; i += 2) all0 &= (p[i] == 0);
        s64 = all0;
    }
    __syncthreads();
    int e = blockIdx.x * blockDim.x + threadIdx.x;
    if (e >= NE) return;
    if (s64) {
        const long long* p = (const long long*)ei;
        g_src[e] = (int)p[e];
        g_dst[e] = (int)p[NE + e];
    } else {
        const int* p = (const int*)ei;
        g_src[e] = p[e];
        g_dst[e] = p[NE + e];
    }
}

// ---------------------------------------------------------------------------
// CSR build: histogram -> 2-level exclusive scan -> bucket fill
// ---------------------------------------------------------------------------
__global__ void zcnt_kernel() {
    int i = blockIdx.x * blockDim.x + threadIdx.x;
    if (i < NN) g_cnt[i] = 0;
}

__global__ void hist_kernel() {
    int e = blockIdx.x * blockDim.x + threadIdx.x;
    if (e < NE) atomicAdd(&g_cnt[g_dst[e]], 1);
}

__global__ void scan_block_kernel() {
    __shared__ int sd[256];
    int tid = threadIdx.x;
    int i = blockIdx.x * 256 + tid;
    int v = (i < NN) ? g_cnt[i] : 0;
    sd[tid] = v;
    __syncthreads();
#pragma unroll
    for (int o = 1; o < 256; o <<= 1) {
        int t = (tid >= o) ? sd[tid - o] : 0;
        __syncthreads();
        sd[tid] += t;
        __syncthreads();
    }
    if (i < NN) g_roff[i] = sd[tid] - v;     // exclusive, pre-offset
    if (tid == 255) g_part[blockIdx.x] = sd[255];
}

__global__ void scan_part_kernel() {
    __shared__ int sd[512];
    int tid = threadIdx.x;
    int v = (tid < NBLK) ? g_part[tid] : 0;
    sd[tid] = v;
    __syncthreads();
#pragma unroll
    for (int o = 1; o < 512; o <<= 1) {
        int t = (tid >= o) ? sd[tid - o] : 0;
        __syncthreads();
        sd[tid] += t;
        __syncthreads();
    }
    if (tid < NBLK) g_poff[tid] = sd[tid] - v;
}

__global__ void scan_add_kernel() {
    int i = blockIdx.x * blockDim.x + threadIdx.x;
    if (i < NN) {
        int r = g_roff[i] + g_poff[i >> 8];
        g_roff[i] = r;
        g_cursor[i] = r;
    }
    if (i == 0) g_roff[NN] = NE;
}

__global__ void fill_kernel(const float* __restrict__ ea) {
    int e = blockIdx.x * blockDim.x + threadIdx.x;
    if (e >= NE) return;
    int d = g_dst[e];
    int p = atomicAdd(&g_cursor[d], 1);
    g_csr_src[p] = g_src[e];
    g_csr_a[p] = ea[e];
}

// ---------------------------------------------------------------------------
// Gather-reduce edge phase: one warp per destination node (2-edge unroll,
// the R5-proven form). agg[n] = (1+eps)*h[n] + sum relu(h[src]+a*We+be).
// Also zeroes the BN stat accumulators (block 0).
// ---------------------------------------------------------------------------
__global__ void __launch_bounds__(256) gather_kernel(
    const float* __restrict__ h,
    const float* __restrict__ We_l,
    const float* __restrict__ be_l,
    const float* __restrict__ eps_l) {
    if (blockIdx.x == 0 && threadIdx.x < DD) {
        g_sum[threadIdx.x] = 0.f;
        g_sumsq[threadIdx.x] = 0.f;
    }
    int node = (blockIdx.x * 256 + threadIdx.x) >> 5;
    if (node >= NN) return;
    int lane = threadIdx.x & 31;
    float4 w  = ((const float4*)We_l)[lane];
    float4 bb = ((const float4*)be_l)[lane];
    float s = 1.0f + __ldg(eps_l);
    float4 hv = ((const float4*)h)[node * 32 + lane];
    float4 acc = make_float4(s * hv.x, s * hv.y, s * hv.z, s * hv.w);

    int i = g_roff[node];
    int end = g_roff[node + 1];
    for (; i + 2 <= end; i += 2) {
        int s0 = g_csr_src[i], s1 = g_csr_src[i + 1];
        float a0 = g_csr_a[i], a1 = g_csr_a[i + 1];
        float4 x0 = ((const float4*)h)[s0 * 32 + lane];
        float4 x1 = ((const float4*)h)[s1 * 32 + lane];
        acc.x += fmaxf(x0.x + fmaf(a0, w.x, bb.x), 0.f)
               + fmaxf(x1.x + fmaf(a1, w.x, bb.x), 0.f);
        acc.y += fmaxf(x0.y + fmaf(a0, w.y, bb.y), 0.f)
               + fmaxf(x1.y + fmaf(a1, w.y, bb.y), 0.f);
        acc.z += fmaxf(x0.z + fmaf(a0, w.z, bb.z), 0.f)
               + fmaxf(x1.z + fmaf(a1, w.z, bb.z), 0.f);
        acc.w += fmaxf(x0.w + fmaf(a0, w.w, bb.w), 0.f)
               + fmaxf(x1.w + fmaf(a1, w.w, bb.w), 0.f);
    }
    if (i < end) {
        int s0 = g_csr_src[i];
        float a0 = g_csr_a[i];
        float4 x0 = ((const float4*)h)[s0 * 32 + lane];
        acc.x += fmaxf(x0.x + fmaf(a0, w.x, bb.x), 0.f);
        acc.y += fmaxf(x0.y + fmaf(a0, w.y, bb.y), 0.f);
        acc.z += fmaxf(x0.z + fmaf(a0, w.z, bb.z), 0.f);
        acc.w += fmaxf(x0.w + fmaf(a0, w.w, bb.w), 0.f);
    }
    ((float4*)g_agg)[node * 32 + lane] = acc;
}

// ---------------------------------------------------------------------------
// tf32 tensor-core GEMM, 128x128 CTA tile, 8 warps (4M x 2N), warp 32x64.
// (R5-proven mainloop: single A buffer, 2 syncs per k-strip.)
// MODE 1: z = agg @ W + b, fused BN sum/sumsq  -> g_z
// MODE 2: out = [res +] relu( relu(BN(z)) @ W + b ) -> outp
// ---------------------------------------------------------------------------
template <int MODE>
__global__ void __launch_bounds__(256, 2) gemm_tc(
    const float* __restrict__ W,
    const float* __restrict__ bias,
    const float* __restrict__ aux,    // MODE2: residual
    float* __restrict__ outp,         // MODE2 only
    int add_res) {
    extern __shared__ float sm[];
    float* Ws = sm;                      // [128][W_PAD]
    float* As = sm + 128 * W_PAD;        // [128][A_PAD]
    unsigned* Wu = (unsigned*)Ws;
    unsigned* Au = (unsigned*)As;

    int tid = threadIdx.x;
    int lane = tid & 31, wid = tid >> 5;
    int wm = wid & 3, wn = wid >> 2;
    int g = lane >> 2, t = lane & 3;
    int row0 = blockIdx.x * BM;

    {
        int r = tid >> 5, c = lane * 4;
#pragma unroll
        for (int p = 0; p < 16; p++) {
            int row = r + p * 8;
            float4 v = *(const float4*)&W[row * DD + c];
            uint4 u = make_uint4(f2tf(v.x), f2tf(v.y), f2tf(v.z), f2tf(v.w));
            *(uint4*)&Wu[row * W_PAD + c] = u;
        }
    }

    float acc[2][8][4];
#pragma unroll
    for (int mi = 0; mi < 2; mi++)
#pragma unroll
        for (int ni = 0; ni < 8; ni++)
#pragma unroll
            for (int q = 0; q < 4; q++) acc[mi][ni][q] = 0.f;

    for (int ko = 0; ko < 4; ko++) {
        __syncthreads();
        {
            int r = tid >> 3, c = (tid & 7) * 4;
#pragma unroll
            for (int p = 0; p < 4; p++) {
                int rr = r + p * 32;
                int row = row0 + rr;
                float4 v = make_float4(0.f, 0.f, 0.f, 0.f);
                if (row < NN) {
                    int off = row * DD + ko * 32 + c;
                    if (MODE == 1) {
                        v = *(const float4*)&g_agg[off];
                    } else {
                        float4 z = *(const float4*)&g_z[off];
                        float4 sc = *(const float4*)&g_scale[ko * 32 + c];
                        float4 sh = *(const float4*)&g_shift[ko * 32 + c];
                        v.x = fmaxf(fmaf(z.x, sc.x, sh.x), 0.f);
                        v.y = fmaxf(fmaf(z.y, sc.y, sh.y), 0.f);
                        v.z = fmaxf(fmaf(z.z, sc.z, sh.z), 0.f);
                        v.w = fmaxf(fmaf(z.w, sc.w, sh.w), 0.f);
                    }
                }
                uint4 u = make_uint4(f2tf(v.x), f2tf(v.y), f2tf(v.z), f2tf(v.w));
                *(uint4*)&Au[rr * A_PAD + c] = u;
            }
        }
        __syncthreads();
#pragma unroll
        for (int kk = 0; kk < 4; kk++) {
            int kb = kk * 8;
            int kw = ko * 32 + kb;
            unsigned b0[8], b1[8];
#pragma unroll
            for (int ni = 0; ni < 8; ni++) {
                int col = wn * 64 + ni * 8 + g;
                b0[ni] = Wu[(kw + t) * W_PAD + col];
                b1[ni] = Wu[(kw + t + 4) * W_PAD + col];
            }
#pragma unroll
            for (int mi = 0; mi < 2; mi++) {
                int rb = wm * 32 + mi * 16;
                unsigned a0 = Au[(rb + g) * A_PAD + kb + t];
                unsigned a1 = Au[(rb + g + 8) * A_PAD + kb + t];
                unsigned a2 = Au[(rb + g) * A_PAD + kb + t + 4];
                unsigned a3 = Au[(rb + g + 8) * A_PAD + kb + t + 4];
#pragma unroll
                for (int ni = 0; ni < 8; ni++)
                    mma8(acc[mi][ni], a0, a1, a2, a3, b0[ni], b1[ni]);
            }
        }
    }

    float bcol[16];
#pragma unroll
    for (int ni = 0; ni < 8; ni++) {
        int col = wn * 64 + ni * 8 + 2 * t;
        bcol[ni * 2]     = __ldg(&bias[col]);
        bcol[ni * 2 + 1] = __ldg(&bias[col + 1]);
    }

    if (MODE == 1) {
        float psum[16], psq[16];
#pragma unroll
        for (int i = 0; i < 16; i++) { psum[i] = 0.f; psq[i] = 0.f; }
#pragma unroll
        for (int mi = 0; mi < 2; mi++) {
            int r1 = row0 + wm * 32 + mi * 16 + g;
            int r2 = r1 + 8;
#pragma unroll
            for (int ni = 0; ni < 8; ni++) {
                int col = wn * 64 + ni * 8 + 2 * t;
                float x0 = acc[mi][ni][0] + bcol[ni * 2];
                float x1 = acc[mi][ni][1] + bcol[ni * 2 + 1];
                float x2 = acc[mi][ni][2] + bcol[ni * 2];
                float x3 = acc[mi][ni][3] + bcol[ni * 2 + 1];
                if (r1 < NN) {
                    *(float2*)&g_z[r1 * DD + col] = make_float2(x0, x1);
                    psum[ni * 2] += x0;     psq[ni * 2] += x0 * x0;
                    psum[ni * 2 + 1] += x1; psq[ni * 2 + 1] += x1 * x1;
                }
                if (r2 < NN) {
                    *(float2*)&g_z[r2 * DD + col] = make_float2(x2, x3);
                    psum[ni * 2] += x2;     psq[ni * 2] += x2 * x2;
                    psum[ni * 2 + 1] += x3; psq[ni * 2 + 1] += x3 * x3;
                }
            }
        }
#pragma unroll
        for (int d = 4; d < 32; d <<= 1) {
#pragma unroll
            for (int i = 0; i < 16; i++) {
                psum[i] += __shfl_down_sync(0xFFFFFFFFu, psum[i], d);
                psq[i]  += __shfl_down_sync(0xFFFFFFFFu, psq[i], d);
            }
        }
        __syncthreads();
        float* ssum = As;
        float* ssq  = As + DD;
        if (tid < DD) { ssum[tid] = 0.f; ssq[tid] = 0.f; }
        __syncthreads();
        if (lane < 4) {
#pragma unroll
            for (int i = 0; i < 16; i++) {
                int col = wn * 64 + (i >> 1) * 8 + 2 * t + (i & 1);
                atomicAdd(&ssum[col], psum[i]);
                atomicAdd(&ssq[col],  psq[i]);
            }
        }
        __syncthreads();
        if (tid < DD) {
            atomicAdd(&g_sum[tid],   ssum[tid]);
            atomicAdd(&g_sumsq[tid], ssq[tid]);
        }
    } else {
#pragma unroll
        for (int mi = 0; mi < 2; mi++) {
            int r1 = row0 + wm * 32 + mi * 16 + g;
            int r2 = r1 + 8;
#pragma unroll
            for (int ni = 0; ni < 8; ni++) {
                int col = wn * 64 + ni * 8 + 2 * t;
                float x0 = fmaxf(acc[mi][ni][0] + bcol[ni * 2], 0.f);
                float x1 = fmaxf(acc[mi][ni][1] + bcol[ni * 2 + 1], 0.f);
                float x2 = fmaxf(acc[mi][ni][2] + bcol[ni * 2], 0.f);
                float x3 = fmaxf(acc[mi][ni][3] + bcol[ni * 2 + 1], 0.f);
                if (r1 < NN) {
                    if (add_res) {
                        float2 rv = *(const float2*)&aux[r1 * DD + col];
                        x0 += rv.x; x1 += rv.y;
                    }
                    *(float2*)&outp[r1 * DD + col] = make_float2(x0, x1);
                }
                if (r2 < NN) {
                    if (add_res) {
                        float2 rv = *(const float2*)&aux[r2 * DD + col];
                        x2 += rv.x; x3 += rv.y;
                    }
                    *(float2*)&outp[r2 * DD + col] = make_float2(x2, x3);
                }
            }
        }
    }
}

// ---------------------------------------------------------------------------
__global__ void finalize_kernel(const float* __restrict__ gamma,
                                const float* __restrict__ beta) {
    int tt = threadIdx.x;
    if (tt < DD) {
        float mu = g_sum[tt] * (1.0f / NN);
        float var = g_sumsq[tt] * (1.0f / NN) - mu * mu;
        float rs = rsqrtf(var + 1e-5f);
        float sc = rs * gamma[tt];
        g_scale[tt] = sc;
        g_shift[tt] = beta[tt] - mu * sc;
    }
}

// ---------------------------------------------------------------------------
extern "C" void kernel_launch(void* const* d_in, const int* in_sizes, int n_in,
                              void* d_out, int out_size) {
    const float* x     = (const float*)d_in[0];
    const void*  ei    = d_in[1];
    const float* ea    = (const float*)d_in[2];
    const float* We    = (const float*)d_in[3];
    const float* be    = (const float*)d_in[4];
    const float* eps   = (const float*)d_in[5];
    const float* W1    = (const float*)d_in[6];
    const float* b1    = (const float*)d_in[7];
    const float* gamma = (const float*)d_in[8];
    const float* beta  = (const float*)d_in[9];
    const float* W2    = (const float*)d_in[10];
    const float* b2    = (const float*)d_in[11];

    void* hp;
    cudaGetSymbolAddress(&hp, g_h);
    float* gh = (float*)hp;

    cudaFuncSetAttribute(gemm_tc<1>, cudaFuncAttributeMaxDynamicSharedMemorySize, GSMEM);
    cudaFuncSetAttribute(gemm_tc<2>, cudaFuncAttributeMaxDynamicSharedMemorySize, GSMEM);

    // edge-index conversion + CSR build (per launch; graph is static input)
    convert_kernel<<<(NE + 255) / 256, 256>>>(ei);
    zcnt_kernel<<<NBLK, 256>>>();
    hist_kernel<<<(NE + 255) / 256, 256>>>();
    scan_block_kernel<<<NBLK, 256>>>();
    scan_part_kernel<<<1, 512>>>();
    scan_add_kernel<<<NBLK, 256>>>();
    fill_kernel<<<(NE + 255) / 256, 256>>>(ea);

    for (int l = 0; l < LL; l++) {
        const float* h_in = (l == 0) ? x : gh;
        float* h_out = (l == LL - 1) ? (float*)d_out : gh;
        gather_kernel<<<(NN * 32) / 256, 256>>>(h_in, We + l * DD, be + l * DD,
                                                eps + l);
        gemm_tc<1><<<MB, 256, GSMEM>>>(W1 + l * DD * DD, b1 + l * DD,
                                       nullptr, nullptr, 0);
        finalize_kernel<<<1, 128>>>(gamma + l * DD, beta + l * DD);
        gemm_tc<2><<<MB, 256, GSMEM>>>(W2 + l * DD * DD, b2 + l * DD,
                                       h_in, h_out, l > 0 ? 1 : 0);
    }
}